// round 1
// baseline (speedup 1.0000x reference)
#include <cuda_runtime.h>
#include <math.h>

#define BATCH 4
#define NPTS  40960
#define KNN   16
#define P_TOTAL (BATCH * NPTS)   // 163840

// Scratch (device globals: no allocation allowed in kernel_launch)
__device__ float g_f_pc [P_TOTAL * 32];                 // 21 MB
__device__ float g_f_agg[P_TOTAL * 32];                 // 21 MB
__device__ float g_f_xyz2[(size_t)P_TOTAL * KNN * 32];  // 335 MB

// ---------------------------------------------------------------------------
// Kernel 1: f_pc = ReLU((feature @ w_mlp1) * s + b)   [B,N,32] -> [B,N,32]
// warp per point; feature row staged in smem, channel per lane.
// ---------------------------------------------------------------------------
__global__ __launch_bounds__(256) void kern_mlp1(
    const float* __restrict__ feature,
    const float* __restrict__ w, const float* __restrict__ s, const float* __restrict__ b)
{
    __shared__ float ws[1024];
    __shared__ float sv[32], bv[32];
    __shared__ float xs[8][32];

    for (int i = threadIdx.x; i < 1024; i += blockDim.x) ws[i] = w[i];
    if (threadIdx.x < 32) { sv[threadIdx.x] = s[threadIdx.x]; bv[threadIdx.x] = b[threadIdx.x]; }
    __syncthreads();

    const int lane = threadIdx.x & 31;
    const int warp = threadIdx.x >> 5;
    const int nwarps = (gridDim.x * blockDim.x) >> 5;
    int gw = (blockIdx.x * blockDim.x + threadIdx.x) >> 5;

    for (int p = gw; p < P_TOTAL; p += nwarps) {
        xs[warp][lane] = feature[(size_t)p * 32 + lane];
        __syncwarp();
        float acc = 0.f;
        #pragma unroll
        for (int j4 = 0; j4 < 32; j4 += 4) {
            float4 f = *(const float4*)(&xs[warp][j4]);
            acc += f.x * ws[(j4 + 0) * 32 + lane];
            acc += f.y * ws[(j4 + 1) * 32 + lane];
            acc += f.z * ws[(j4 + 2) * 32 + lane];
            acc += f.w * ws[(j4 + 3) * 32 + lane];
        }
        g_f_pc[(size_t)p * 32 + lane] = fmaxf(acc * sv[lane] + bv[lane], 0.f);
        __syncwarp();
    }
}

// ---------------------------------------------------------------------------
// Kernel 2: rel_pos + lfa1 + gather(f_pc) + att1 (fc, softmax, pool, mlp)
//           -> g_f_agg ;  lfa2(f_xyz) -> g_f_xyz2
// warp per point. fs [16,64] tile in per-warp smem.
// ---------------------------------------------------------------------------
#define K2_WARP_FLOATS 1248   // fs 1024 + rp 160 + agg 64
#define K2_BASE_FLOATS 7680
#define K2_SMEM_BYTES ((K2_BASE_FLOATS + 8 * K2_WARP_FLOATS) * 4)

__global__ __launch_bounds__(256) void kern_att1(
    const float* __restrict__ xyz, const int* __restrict__ neigh,
    const float* __restrict__ wlfa1, const float* __restrict__ slfa1, const float* __restrict__ blfa1,
    const float* __restrict__ wfc1,
    const float* __restrict__ wam1, const float* __restrict__ sam1, const float* __restrict__ bam1,
    const float* __restrict__ wlfa2, const float* __restrict__ slfa2, const float* __restrict__ blfa2)
{
    extern __shared__ float sm[];
    float* s_wfc = sm;            // 4096  wfc1  [64][64]
    float* s_wam = sm + 4096;     // 2048  wam1  [64][32]
    float* s_wl2 = sm + 6144;     // 1024  wlfa2 [32][32]
    float* s_wl1 = sm + 7168;     // 320   wlfa1 [10][32]
    float* s_vec = sm + 7488;     // 192
    float* s_wrp = sm + K2_BASE_FLOATS;

    for (int i = threadIdx.x; i < 4096; i += blockDim.x) s_wfc[i] = wfc1[i];
    for (int i = threadIdx.x; i < 2048; i += blockDim.x) s_wam[i] = wam1[i];
    for (int i = threadIdx.x; i < 1024; i += blockDim.x) s_wl2[i] = wlfa2[i];
    for (int i = threadIdx.x; i < 320;  i += blockDim.x) s_wl1[i] = wlfa1[i];
    if (threadIdx.x < 32) {
        int l = threadIdx.x;
        s_vec[l]       = slfa1[l];  s_vec[32 + l]  = blfa1[l];
        s_vec[64 + l]  = sam1[l];   s_vec[96 + l]  = bam1[l];
        s_vec[128 + l] = slfa2[l];  s_vec[160 + l] = blfa2[l];
    }
    __syncthreads();

    const int lane = threadIdx.x & 31;
    const int warp = threadIdx.x >> 5;
    float* fs_s  = s_wrp + warp * K2_WARP_FLOATS;
    float* rp_s  = fs_s + 1024;
    float* agg_s = rp_s + 160;

    const int nwarps = (gridDim.x * blockDim.x) >> 5;
    int gw = (blockIdx.x * blockDim.x + threadIdx.x) >> 5;

    for (int p = gw; p < P_TOTAL; p += nwarps) {
        const int b = p / NPTS;
        const size_t bbase = (size_t)b * NPTS;

        int myidx = 0;
        if (lane < KNN) myidx = neigh[(size_t)p * KNN + lane];

        const float cx = xyz[(size_t)p * 3 + 0];
        const float cy = xyz[(size_t)p * 3 + 1];
        const float cz = xyz[(size_t)p * 3 + 2];

        if (lane < KNN) {
            size_t nb = bbase + (size_t)myidx;
            float nx = xyz[nb * 3 + 0], ny = xyz[nb * 3 + 1], nz = xyz[nb * 3 + 2];
            float rx = cx - nx, ry = cy - ny, rz = cz - nz;
            float d = sqrtf(rx * rx + ry * ry + rz * rz);
            float* rp = rp_s + lane * 10;
            rp[0] = d;  rp[1] = rx; rp[2] = ry; rp[3] = rz;
            rp[4] = cx; rp[5] = cy; rp[6] = cz;
            rp[7] = nx; rp[8] = ny; rp[9] = nz;
        }
        __syncwarp();

        // f_xyz[k][lane] = ReLU(relpos @ wlfa1)  -> fs[:,32+lane]
        float fxyz[KNN];
        {
            const float sl = s_vec[lane], bl = s_vec[32 + lane];
            #pragma unroll
            for (int k = 0; k < KNN; k++) {
                float acc = 0.f;
                #pragma unroll
                for (int j = 0; j < 10; j++) acc += rp_s[k * 10 + j] * s_wl1[j * 32 + lane];
                float v = fmaxf(acc * sl + bl, 0.f);
                fxyz[k] = v;
                fs_s[k * 64 + 32 + lane] = v;
            }
        }
        // f_nb[k][lane] = gather(f_pc)  -> fs[:,lane]
        float fnb[KNN];
        #pragma unroll
        for (int k = 0; k < KNN; k++) {
            int nb = __shfl_sync(0xffffffffu, myidx, k);
            float v = g_f_pc[(bbase + (size_t)nb) * 32 + lane];
            fnb[k] = v;
            fs_s[k * 64 + lane] = v;
        }
        __syncwarp();

        // logits L[k][lane], L[k][lane+32]
        float accL[KNN], accH[KNN];
        #pragma unroll
        for (int k = 0; k < KNN; k++) { accL[k] = 0.f; accH[k] = 0.f; }
        for (int j4 = 0; j4 < 64; j4 += 4) {
            float wl0 = s_wfc[(j4 + 0) * 64 + lane];
            float wl1 = s_wfc[(j4 + 1) * 64 + lane];
            float wl2 = s_wfc[(j4 + 2) * 64 + lane];
            float wl3 = s_wfc[(j4 + 3) * 64 + lane];
            float wh0 = s_wfc[(j4 + 0) * 64 + 32 + lane];
            float wh1 = s_wfc[(j4 + 1) * 64 + 32 + lane];
            float wh2 = s_wfc[(j4 + 2) * 64 + 32 + lane];
            float wh3 = s_wfc[(j4 + 3) * 64 + 32 + lane];
            #pragma unroll
            for (int k = 0; k < KNN; k++) {
                float4 f = *(const float4*)(fs_s + k * 64 + j4);
                accL[k] += f.x * wl0; accL[k] += f.y * wl1;
                accL[k] += f.z * wl2; accL[k] += f.w * wl3;
                accH[k] += f.x * wh0; accH[k] += f.y * wh1;
                accH[k] += f.z * wh2; accH[k] += f.w * wh3;
            }
        }

        // lane-local softmax over K + attention pool (channels lane, lane+32)
        float aggL, aggH;
        {
            float m = -1e30f;
            #pragma unroll
            for (int k = 0; k < KNN; k++) m = fmaxf(m, accL[k]);
            float ssum = 0.f;
            #pragma unroll
            for (int k = 0; k < KNN; k++) { float e = __expf(accL[k] - m); accL[k] = e; ssum += e; }
            float a = 0.f;
            #pragma unroll
            for (int k = 0; k < KNN; k++) a += fnb[k] * accL[k];
            aggL = a / ssum;
        }
        {
            float m = -1e30f;
            #pragma unroll
            for (int k = 0; k < KNN; k++) m = fmaxf(m, accH[k]);
            float ssum = 0.f;
            #pragma unroll
            for (int k = 0; k < KNN; k++) { float e = __expf(accH[k] - m); accH[k] = e; ssum += e; }
            float a = 0.f;
            #pragma unroll
            for (int k = 0; k < KNN; k++) a += fxyz[k] * accH[k];
            aggH = a / ssum;
        }
        agg_s[lane] = aggL;
        agg_s[32 + lane] = aggH;
        __syncwarp();

        // f_agg = ReLU((agg @ wam1)*s + b), channel = lane
        {
            float acc = 0.f;
            #pragma unroll
            for (int d4 = 0; d4 < 64; d4 += 4) {
                float4 a = *(const float4*)(agg_s + d4);
                acc += a.x * s_wam[(d4 + 0) * 32 + lane];
                acc += a.y * s_wam[(d4 + 1) * 32 + lane];
                acc += a.z * s_wam[(d4 + 2) * 32 + lane];
                acc += a.w * s_wam[(d4 + 3) * 32 + lane];
            }
            g_f_agg[(size_t)p * 32 + lane] = fmaxf(acc * s_vec[64 + lane] + s_vec[96 + lane], 0.f);
        }

        // f_xyz2 = ReLU((f_xyz @ wlfa2)*s + b) -> scratch
        {
            float wcol[32];
            #pragma unroll
            for (int j = 0; j < 32; j++) wcol[j] = s_wl2[j * 32 + lane];
            const float sl = s_vec[128 + lane], bl = s_vec[160 + lane];
            #pragma unroll
            for (int k = 0; k < KNN; k++) {
                float acc = 0.f;
                #pragma unroll
                for (int j4 = 0; j4 < 32; j4 += 4) {
                    float4 f = *(const float4*)(fs_s + k * 64 + 32 + j4);
                    acc += f.x * wcol[j4 + 0] + f.y * wcol[j4 + 1]
                         + f.z * wcol[j4 + 2] + f.w * wcol[j4 + 3];
                }
                g_f_xyz2[((size_t)p * KNN + k) * 32 + lane] = fmaxf(acc * sl + bl, 0.f);
            }
        }
        __syncwarp();
    }
}

// ---------------------------------------------------------------------------
// Kernel 3: gather(f_agg) + f_xyz2 + att2 + att2_mlp + mlp2 + shortcut + leaky
// ---------------------------------------------------------------------------
#define K3_WARP_FLOATS 1184   // fs 1024 + agg 64 + pc2 64 + feat 32
#define K3_BASE_FLOATS 21120
#define K3_SMEM_BYTES ((K3_BASE_FLOATS + 16 * K3_WARP_FLOATS) * 4)

__global__ __launch_bounds__(512) void kern_att2(
    const float* __restrict__ feature, const int* __restrict__ neigh,
    const float* __restrict__ wfc2,
    const float* __restrict__ wam2, const float* __restrict__ sam2, const float* __restrict__ bam2,
    const float* __restrict__ wmlp2, const float* __restrict__ smlp2, const float* __restrict__ bmlp2,
    const float* __restrict__ wsc, const float* __restrict__ ssc, const float* __restrict__ bsc,
    float* __restrict__ out)
{
    extern __shared__ float sm[];
    float* s_wfc = sm;             // 4096  [64][64]
    float* s_wam = sm + 4096;      // 4096  [64][64]
    float* s_wm2 = sm + 8192;      // 8192  [64][128]
    float* s_wsc = sm + 16384;     // 4096  [32][128]
    float* s_vec = sm + 20480;     // 640
    float* s_wrp = sm + K3_BASE_FLOATS;

    for (int i = threadIdx.x; i < 4096; i += blockDim.x) s_wfc[i] = wfc2[i];
    for (int i = threadIdx.x; i < 4096; i += blockDim.x) s_wam[i] = wam2[i];
    for (int i = threadIdx.x; i < 8192; i += blockDim.x) s_wm2[i] = wmlp2[i];
    for (int i = threadIdx.x; i < 4096; i += blockDim.x) s_wsc[i] = wsc[i];
    if (threadIdx.x < 64) {
        int l = threadIdx.x;
        s_vec[l] = sam2[l]; s_vec[64 + l] = bam2[l];
    }
    if (threadIdx.x < 128) {
        int l = threadIdx.x;
        s_vec[128 + l] = smlp2[l]; s_vec[256 + l] = bmlp2[l];
        s_vec[384 + l] = ssc[l];   s_vec[512 + l] = bsc[l];
    }
    __syncthreads();

    const int lane = threadIdx.x & 31;
    const int warp = threadIdx.x >> 5;
    float* fs_s   = s_wrp + warp * K3_WARP_FLOATS;
    float* agg_s  = fs_s + 1024;
    float* pc2_s  = fs_s + 1088;
    float* feat_s = fs_s + 1152;

    const int nwarps = (gridDim.x * blockDim.x) >> 5;
    int gw = (blockIdx.x * blockDim.x + threadIdx.x) >> 5;

    for (int p = gw; p < P_TOTAL; p += nwarps) {
        const int b = p / NPTS;
        const size_t bbase = (size_t)b * NPTS;

        int myidx = 0;
        if (lane < KNN) myidx = neigh[(size_t)p * KNN + lane];

        float fnb2[KNN], fx2[KNN];
        #pragma unroll
        for (int k = 0; k < KNN; k++) {
            int nb = __shfl_sync(0xffffffffu, myidx, k);
            float v = g_f_agg[(bbase + (size_t)nb) * 32 + lane];
            fnb2[k] = v;
            fs_s[k * 64 + lane] = v;
        }
        #pragma unroll
        for (int k = 0; k < KNN; k++) {
            float v = g_f_xyz2[((size_t)p * KNN + k) * 32 + lane];
            fx2[k] = v;
            fs_s[k * 64 + 32 + lane] = v;
        }
        feat_s[lane] = feature[(size_t)p * 32 + lane];
        __syncwarp();

        // logits vs wfc2
        float accL[KNN], accH[KNN];
        #pragma unroll
        for (int k = 0; k < KNN; k++) { accL[k] = 0.f; accH[k] = 0.f; }
        for (int j4 = 0; j4 < 64; j4 += 4) {
            float wl0 = s_wfc[(j4 + 0) * 64 + lane];
            float wl1 = s_wfc[(j4 + 1) * 64 + lane];
            float wl2 = s_wfc[(j4 + 2) * 64 + lane];
            float wl3 = s_wfc[(j4 + 3) * 64 + lane];
            float wh0 = s_wfc[(j4 + 0) * 64 + 32 + lane];
            float wh1 = s_wfc[(j4 + 1) * 64 + 32 + lane];
            float wh2 = s_wfc[(j4 + 2) * 64 + 32 + lane];
            float wh3 = s_wfc[(j4 + 3) * 64 + 32 + lane];
            #pragma unroll
            for (int k = 0; k < KNN; k++) {
                float4 f = *(const float4*)(fs_s + k * 64 + j4);
                accL[k] += f.x * wl0; accL[k] += f.y * wl1;
                accL[k] += f.z * wl2; accL[k] += f.w * wl3;
                accH[k] += f.x * wh0; accH[k] += f.y * wh1;
                accH[k] += f.z * wh2; accH[k] += f.w * wh3;
            }
        }

        float aggL, aggH;
        {
            float m = -1e30f;
            #pragma unroll
            for (int k = 0; k < KNN; k++) m = fmaxf(m, accL[k]);
            float ssum = 0.f;
            #pragma unroll
            for (int k = 0; k < KNN; k++) { float e = __expf(accL[k] - m); accL[k] = e; ssum += e; }
            float a = 0.f;
            #pragma unroll
            for (int k = 0; k < KNN; k++) a += fnb2[k] * accL[k];
            aggL = a / ssum;
        }
        {
            float m = -1e30f;
            #pragma unroll
            for (int k = 0; k < KNN; k++) m = fmaxf(m, accH[k]);
            float ssum = 0.f;
            #pragma unroll
            for (int k = 0; k < KNN; k++) { float e = __expf(accH[k] - m); accH[k] = e; ssum += e; }
            float a = 0.f;
            #pragma unroll
            for (int k = 0; k < KNN; k++) a += fx2[k] * accH[k];
            aggH = a / ssum;
        }
        agg_s[lane] = aggL;
        agg_s[32 + lane] = aggH;
        __syncwarp();

        // f_pc2 = ReLU((agg @ wam2)*s + b), channels lane and lane+32
        {
            float accl = 0.f, acch = 0.f;
            #pragma unroll
            for (int d4 = 0; d4 < 64; d4 += 4) {
                float4 a = *(const float4*)(agg_s + d4);
                accl += a.x * s_wam[(d4 + 0) * 64 + lane];
                accl += a.y * s_wam[(d4 + 1) * 64 + lane];
                accl += a.z * s_wam[(d4 + 2) * 64 + lane];
                accl += a.w * s_wam[(d4 + 3) * 64 + lane];
                acch += a.x * s_wam[(d4 + 0) * 64 + 32 + lane];
                acch += a.y * s_wam[(d4 + 1) * 64 + 32 + lane];
                acch += a.z * s_wam[(d4 + 2) * 64 + 32 + lane];
                acch += a.w * s_wam[(d4 + 3) * 64 + 32 + lane];
            }
            pc2_s[lane]      = fmaxf(accl * s_vec[lane]      + s_vec[64 + lane],      0.f);
            pc2_s[32 + lane] = fmaxf(acch * s_vec[32 + lane] + s_vec[96 + lane],      0.f);
        }
        __syncwarp();

        // out = leaky( (f_pc2 @ wmlp2)*s+b + (feature @ wsc)*s+b )
        #pragma unroll
        for (int ci = 0; ci < 4; ci++) {
            int c = lane + ci * 32;
            float o = 0.f;
            #pragma unroll
            for (int d4 = 0; d4 < 64; d4 += 4) {
                float4 a = *(const float4*)(pc2_s + d4);
                o += a.x * s_wm2[(d4 + 0) * 128 + c];
                o += a.y * s_wm2[(d4 + 1) * 128 + c];
                o += a.z * s_wm2[(d4 + 2) * 128 + c];
                o += a.w * s_wm2[(d4 + 3) * 128 + c];
            }
            float scv = 0.f;
            #pragma unroll
            for (int j4 = 0; j4 < 32; j4 += 4) {
                float4 f = *(const float4*)(feat_s + j4);
                scv += f.x * s_wsc[(j4 + 0) * 128 + c];
                scv += f.y * s_wsc[(j4 + 1) * 128 + c];
                scv += f.z * s_wsc[(j4 + 2) * 128 + c];
                scv += f.w * s_wsc[(j4 + 3) * 128 + c];
            }
            float v = o * s_vec[128 + c] + s_vec[256 + c]
                    + scv * s_vec[384 + c] + s_vec[512 + c];
            out[(size_t)p * 128 + c] = (v < 0.f) ? 0.2f * v : v;
        }
        __syncwarp();
    }
}

// ---------------------------------------------------------------------------
extern "C" void kernel_launch(void* const* d_in, const int* in_sizes, int n_in,
                              void* d_out, int out_size)
{
    const float* feature = (const float*)d_in[0];
    const float* xyz     = (const float*)d_in[1];
    const int*   neigh   = (const int*)  d_in[2];
    const float* w_mlp1  = (const float*)d_in[3];
    const float* s_mlp1  = (const float*)d_in[4];
    const float* b_mlp1  = (const float*)d_in[5];
    const float* w_lfa1  = (const float*)d_in[6];
    const float* s_lfa1  = (const float*)d_in[7];
    const float* b_lfa1  = (const float*)d_in[8];
    const float* w_fc1   = (const float*)d_in[9];
    const float* w_am1   = (const float*)d_in[10];
    const float* s_am1   = (const float*)d_in[11];
    const float* b_am1   = (const float*)d_in[12];
    const float* w_lfa2  = (const float*)d_in[13];
    const float* s_lfa2  = (const float*)d_in[14];
    const float* b_lfa2  = (const float*)d_in[15];
    const float* w_fc2   = (const float*)d_in[16];
    const float* w_am2   = (const float*)d_in[17];
    const float* s_am2   = (const float*)d_in[18];
    const float* b_am2   = (const float*)d_in[19];
    const float* w_mlp2  = (const float*)d_in[20];
    const float* s_mlp2  = (const float*)d_in[21];
    const float* b_mlp2  = (const float*)d_in[22];
    const float* w_sc    = (const float*)d_in[23];
    const float* s_sc    = (const float*)d_in[24];
    const float* b_sc    = (const float*)d_in[25];
    float* out = (float*)d_out;

    cudaFuncSetAttribute(kern_att1, cudaFuncAttributeMaxDynamicSharedMemorySize, K2_SMEM_BYTES);
    cudaFuncSetAttribute(kern_att2, cudaFuncAttributeMaxDynamicSharedMemorySize, K3_SMEM_BYTES);

    kern_mlp1<<<2048, 256>>>(feature, w_mlp1, s_mlp1, b_mlp1);

    kern_att1<<<2048, 256, K2_SMEM_BYTES>>>(
        xyz, neigh,
        w_lfa1, s_lfa1, b_lfa1,
        w_fc1,
        w_am1, s_am1, b_am1,
        w_lfa2, s_lfa2, b_lfa2);

    kern_att2<<<1024, 512, K3_SMEM_BYTES>>>(
        feature, neigh,
        w_fc2,
        w_am2, s_am2, b_am2,
        w_mlp2, s_mlp2, b_mlp2,
        w_sc, s_sc, b_sc,
        out);
}